// round 4
// baseline (speedup 1.0000x reference)
#include <cuda_runtime.h>
#include <cuda_bf16.h>

// DilatedAttention: B=2, S=8192, D=1024, SEG=2048, rates {1,2,4,8}
// Phase 1: merged QK^T GEMM (all rates), fp32 f32x2 packed FFMA -> scratch
// Phase 2: row softmax (smem-resident) in place on scratch
// Phase 3: P*V GEMMs, r=1 writes '=', r=2/4/8 '+=' (stream-ordered, race-free)
//
// Inner-loop design: A is stored PRE-DUPLICATED in smem ({v,v} 64-bit pairs)
// so the FFMA2 packed multiplier comes straight from LDS.128 -- no per-element
// register dup MOVs. 6 LDS.128 + 32 FFMA2 per k-slice per thread.
// Scratch traffic uses streaming (.cs) hints to avoid evicting Q/K/V from L2.

#define DIM 1024
#define SEG 2048
#define NBG 8   /* B * n_seg = 2*4 */

#define OFF1 0ull
#define OFF2 4194304ull            /* 2048^2 */
#define OFF4 5242880ull            /* +1024^2 */
#define OFF8 5505024ull            /* +512^2 */
#define PER_BG 5570560ull          /* +256^2 */

__device__ __align__(16) float g_S[8ull * PER_BG];  // ~178 MB score scratch

typedef unsigned long long ull;

__device__ __forceinline__ ull fma2(ull a, ull b, ull c) {
    ull d; asm("fma.rn.f32x2 %0, %1, %2, %3;" : "=l"(d) : "l"(a), "l"(b), "l"(c)); return d;
}
__device__ __forceinline__ float2 unpk(ull v) {
    float lo, hi; asm("mov.b64 {%0, %1}, %2;" : "=f"(lo), "=f"(hi) : "l"(v));
    float2 f; f.x = lo; f.y = hi; return f;
}

// ---------------------------------------------------------------------------
// Merged QK^T GEMM: for each rate r, C[LxL] = Qr[Lx1024] * Kr[Lx1024]^T.
// Tile 128x128x16, 256 threads, 8x8 microtile, f32x2 accumulation.
// grid.x encodes (rate, mtile, ntile); grid.y = bg.
// ---------------------------------------------------------------------------
__global__ __launch_bounds__(256, 2) void qk_kernel(
    const float* __restrict__ Q, const float* __restrict__ Kp)
{
    __shared__ __align__(16) float As[2][16][256];   // A pre-duplicated pairs
    __shared__ __align__(16) float Bs[2][16][128];

    int t = blockIdx.x;
    int r, L; ull soff; int mtile, ntile;
    if (t < 256)      {          r = 1; L = 2048; soff = OFF1; mtile = t >> 4; ntile = t & 15; }
    else if (t < 320) { t -= 256; r = 2; L = 1024; soff = OFF2; mtile = t >> 3; ntile = t & 7; }
    else if (t < 336) { t -= 320; r = 4; L = 512;  soff = OFF4; mtile = t >> 2; ntile = t & 3; }
    else              { t -= 336; r = 8; L = 256;  soff = OFF8; mtile = t >> 1; ntile = t & 1; }

    const int tid   = threadIdx.x;
    const int bg    = blockIdx.y;
    const int mbase = mtile * 128;
    const int nbase = ntile * 128;

    const float* Qb = Q  + (size_t)bg * SEG * DIM;
    const float* Kb = Kp + (size_t)bg * SEG * DIM;
    float*       Sp = g_S + (size_t)bg * PER_BG + soff;

    const int lrow = tid >> 2;         // 0..63
    const int kq   = (tid & 3) << 2;   // 0,4,8,12
    const float* ag0  = Qb + (size_t)(mbase + lrow)      * r * DIM + kq;
    const float* ag1  = Qb + (size_t)(mbase + lrow + 64) * r * DIM + kq;
    const float* bgp0 = Kb + (size_t)(nbase + lrow)      * r * DIM + kq;
    const float* bgp1 = Kb + (size_t)(nbase + lrow + 64) * r * DIM + kq;

    const int tx = tid & 15, ty = tid >> 4;

    ull acc[8][4];
    #pragma unroll
    for (int i = 0; i < 8; i++)
        #pragma unroll
        for (int j = 0; j < 4; j++) acc[i][j] = 0ull;

    const int NC = DIM / 16;  // 64
    float4 ra0, ra1, rb0, rb1;

    ra0 = *(const float4*)(ag0);
    ra1 = *(const float4*)(ag1);
    rb0 = *(const float4*)(bgp0);
    rb1 = *(const float4*)(bgp1);
    #pragma unroll
    for (int j = 0; j < 4; j++) {
        float a0 = ((const float*)&ra0)[j], a1 = ((const float*)&ra1)[j];
        *(float2*)&As[0][kq + j][2*lrow]       = make_float2(a0, a0);
        *(float2*)&As[0][kq + j][2*lrow + 128] = make_float2(a1, a1);
        Bs[0][kq + j][lrow]      = ((const float*)&rb0)[j];
        Bs[0][kq + j][lrow + 64] = ((const float*)&rb1)[j];
    }
    __syncthreads();

    for (int c = 0; c < NC; c++) {
        const int cur = c & 1;
        const bool more = (c + 1 < NC);
        if (more) {
            const int kc = (c + 1) * 16;
            ra0 = *(const float4*)(ag0 + kc);
            ra1 = *(const float4*)(ag1 + kc);
            rb0 = *(const float4*)(bgp0 + kc);
            rb1 = *(const float4*)(bgp1 + kc);
        }
        #pragma unroll
        for (int kk = 0; kk < 16; kk++) {
            ull ad[8];
            #pragma unroll
            for (int q4 = 0; q4 < 4; q4++)
                *(ulonglong2*)&ad[q4 * 2] = *(const ulonglong2*)&As[cur][kk][ty * 16 + q4 * 4];
            ulonglong2 b01 = *(const ulonglong2*)&Bs[cur][kk][tx * 8];
            ulonglong2 b23 = *(const ulonglong2*)&Bs[cur][kk][tx * 8 + 4];
            ull bb[4] = { b01.x, b01.y, b23.x, b23.y };
            #pragma unroll
            for (int i = 0; i < 8; i++)
                #pragma unroll
                for (int jp = 0; jp < 4; jp++)
                    acc[i][jp] = fma2(ad[i], bb[jp], acc[i][jp]);
        }
        if (more) {
            const int nxt = cur ^ 1;  // writes disjoint from 'cur' reads: one barrier suffices
            #pragma unroll
            for (int j = 0; j < 4; j++) {
                float a0 = ((const float*)&ra0)[j], a1 = ((const float*)&ra1)[j];
                *(float2*)&As[nxt][kq + j][2*lrow]       = make_float2(a0, a0);
                *(float2*)&As[nxt][kq + j][2*lrow + 128] = make_float2(a1, a1);
                Bs[nxt][kq + j][lrow]      = ((const float*)&rb0)[j];
                Bs[nxt][kq + j][lrow + 64] = ((const float*)&rb1)[j];
            }
            __syncthreads();
        }
    }

    // Streaming stores: scores are consumed once by softmax, don't pollute L2.
    #pragma unroll
    for (int i = 0; i < 8; i++) {
        const int row = mbase + ty * 8 + i;
        float* p = Sp + (size_t)row * L + nbase + tx * 8;
        float2 c0 = unpk(acc[i][0]), c1 = unpk(acc[i][1]);
        float2 c2 = unpk(acc[i][2]), c3 = unpk(acc[i][3]);
        __stcs((float4*)p,       make_float4(c0.x, c0.y, c1.x, c1.y));
        __stcs((float4*)(p + 4), make_float4(c2.x, c2.y, c3.x, c3.y));
    }
}

// ---------------------------------------------------------------------------
// Softmax: one block per score row (30720 rows), smem-resident, in place.
// gmem: read once + write once.
// ---------------------------------------------------------------------------
__global__ __launch_bounds__(256) void softmax_kernel()
{
    __shared__ float buf[2048];
    __shared__ float red[8];

    const int idx = blockIdx.x;
    const int tid = threadIdx.x;
    const int lane = tid & 31, wid = tid >> 5;

    int L; ull base;
    if (idx < 16384)      { int bg = idx >> 11, row = idx & 2047; L = 2048; base = (ull)bg * PER_BG + OFF1 + (ull)row * 2048; }
    else if (idx < 24576) { int j = idx - 16384; int bg = j >> 10, row = j & 1023; L = 1024; base = (ull)bg * PER_BG + OFF2 + (ull)row * 1024; }
    else if (idx < 28672) { int j = idx - 24576; int bg = j >> 9,  row = j & 511;  L = 512;  base = (ull)bg * PER_BG + OFF4 + (ull)row * 512; }
    else                  { int j = idx - 28672; int bg = j >> 8,  row = j & 255;  L = 256;  base = (ull)bg * PER_BG + OFF8 + (ull)row * 256; }

    float* rp = g_S + base;

    float mx = -3.402823466e38f;
    for (int i = tid; i < L; i += 256) {
        float v = __ldcs(rp + i);
        buf[i] = v;
        mx = fmaxf(mx, v);
    }
    #pragma unroll
    for (int s = 16; s > 0; s >>= 1) mx = fmaxf(mx, __shfl_xor_sync(0xffffffffu, mx, s));
    if (lane == 0) red[wid] = mx;
    __syncthreads();
    if (wid == 0) {
        float m = red[lane & 7];
        #pragma unroll
        for (int s = 4; s > 0; s >>= 1) m = fmaxf(m, __shfl_xor_sync(0xffffffffu, m, s));
        if (lane == 0) red[0] = m;
    }
    __syncthreads();
    mx = red[0];

    float sum = 0.f;
    for (int i = tid; i < L; i += 256) {
        float e = __expf(buf[i] - mx);
        buf[i] = e;
        sum += e;
    }
    #pragma unroll
    for (int s = 16; s > 0; s >>= 1) sum += __shfl_xor_sync(0xffffffffu, sum, s);
    __syncthreads();
    if (lane == 0) red[wid] = sum;
    __syncthreads();
    if (wid == 0) {
        float m = red[lane & 7];
        #pragma unroll
        for (int s = 4; s > 0; s >>= 1) m += __shfl_xor_sync(0xffffffffu, m, s);
        if (lane == 0) red[0] = m;
    }
    __syncthreads();
    const float inv = 1.0f / red[0];
    for (int i = tid; i < L; i += 256) __stcs(rp + i, buf[i] * inv);
}

// ---------------------------------------------------------------------------
// P*V GEMM: C[L x 1024] = P[L x L] * V[L x 1024] (V rows strided by r).
// Output rows scattered to q*r; r==1 writes '=', others '+='.
// ---------------------------------------------------------------------------
__global__ __launch_bounds__(256, 2) void pv_kernel(
    const float* __restrict__ V, float* __restrict__ O,
    int r, int L, unsigned long long soff, int accum)
{
    __shared__ __align__(16) float As[2][16][256];   // P pre-duplicated pairs
    __shared__ __align__(16) float Bs[2][16][128];

    const int tid   = threadIdx.x;
    const int bg    = blockIdx.z;
    const int mbase = blockIdx.y * 128;
    const int nbase = blockIdx.x * 128;

    const float* Vb = V + (size_t)bg * SEG * DIM;
    float*       Ob = O + (size_t)bg * SEG * DIM;
    const float* P  = g_S + (size_t)bg * PER_BG + soff;

    const int lrow = tid >> 2;
    const int kq   = (tid & 3) << 2;
    const float* pg0 = P + (size_t)(mbase + lrow)      * L + kq;
    const float* pg1 = P + (size_t)(mbase + lrow + 64) * L + kq;

    const int krow = tid >> 5;          // 0..7
    const int vcol = (tid & 31) << 2;   // 0..124

    const int tx = tid & 15, ty = tid >> 4;

    ull acc[8][4];
    #pragma unroll
    for (int i = 0; i < 8; i++)
        #pragma unroll
        for (int j = 0; j < 4; j++) acc[i][j] = 0ull;

    const int NC = L / 16;
    float4 ra0, ra1, rb0, rb1;

    ra0 = __ldcs((const float4*)(pg0));   // P: streaming, read once
    ra1 = __ldcs((const float4*)(pg1));
    rb0 = *(const float4*)(Vb + (size_t)krow       * r * DIM + nbase + vcol);
    rb1 = *(const float4*)(Vb + (size_t)(krow + 8) * r * DIM + nbase + vcol);
    #pragma unroll
    for (int j = 0; j < 4; j++) {
        float a0 = ((const float*)&ra0)[j], a1 = ((const float*)&ra1)[j];
        *(float2*)&As[0][kq + j][2*lrow]       = make_float2(a0, a0);
        *(float2*)&As[0][kq + j][2*lrow + 128] = make_float2(a1, a1);
    }
    *(float4*)&Bs[0][krow][vcol]     = rb0;
    *(float4*)&Bs[0][krow + 8][vcol] = rb1;
    __syncthreads();

    for (int c = 0; c < NC; c++) {
        const int cur = c & 1;
        const bool more = (c + 1 < NC);
        if (more) {
            const int kc = (c + 1) * 16;
            ra0 = __ldcs((const float4*)(pg0 + kc));
            ra1 = __ldcs((const float4*)(pg1 + kc));
            rb0 = *(const float4*)(Vb + (size_t)(kc + krow)     * r * DIM + nbase + vcol);
            rb1 = *(const float4*)(Vb + (size_t)(kc + krow + 8) * r * DIM + nbase + vcol);
        }
        #pragma unroll
        for (int kk = 0; kk < 16; kk++) {
            ull ad[8];
            #pragma unroll
            for (int q4 = 0; q4 < 4; q4++)
                *(ulonglong2*)&ad[q4 * 2] = *(const ulonglong2*)&As[cur][kk][ty * 16 + q4 * 4];
            ulonglong2 b01 = *(const ulonglong2*)&Bs[cur][kk][tx * 8];
            ulonglong2 b23 = *(const ulonglong2*)&Bs[cur][kk][tx * 8 + 4];
            ull bb[4] = { b01.x, b01.y, b23.x, b23.y };
            #pragma unroll
            for (int i = 0; i < 8; i++)
                #pragma unroll
                for (int jp = 0; jp < 4; jp++)
                    acc[i][jp] = fma2(ad[i], bb[jp], acc[i][jp]);
        }
        if (more) {
            const int nxt = cur ^ 1;
            #pragma unroll
            for (int j = 0; j < 4; j++) {
                float a0 = ((const float*)&ra0)[j], a1 = ((const float*)&ra1)[j];
                *(float2*)&As[nxt][kq + j][2*lrow]       = make_float2(a0, a0);
                *(float2*)&As[nxt][kq + j][2*lrow + 128] = make_float2(a1, a1);
            }
            *(float4*)&Bs[nxt][krow][vcol]     = rb0;
            *(float4*)&Bs[nxt][krow + 8][vcol] = rb1;
            __syncthreads();
        }
    }

    #pragma unroll
    for (int i = 0; i < 8; i++) {
        const int qrow = mbase + ty * 8 + i;
        float* p = Ob + (size_t)qrow * r * DIM + nbase + tx * 8;
        float2 c0 = unpk(acc[i][0]), c1 = unpk(acc[i][1]);
        float2 c2 = unpk(acc[i][2]), c3 = unpk(acc[i][3]);
        float4 v0 = make_float4(c0.x, c0.y, c1.x, c1.y);
        float4 v1 = make_float4(c2.x, c2.y, c3.x, c3.y);
        if (accum) {
            float4 o0 = *(float4*)p;
            float4 o1 = *(float4*)(p + 4);
            v0.x += o0.x; v0.y += o0.y; v0.z += o0.z; v0.w += o0.w;
            v1.x += o1.x; v1.y += o1.y; v1.z += o1.z; v1.w += o1.w;
        }
        *(float4*)p       = v0;
        *(float4*)(p + 4) = v1;
    }
}

extern "C" void kernel_launch(void* const* d_in, const int* in_sizes, int n_in,
                              void* d_out, int out_size)
{
    const float* Q = (const float*)d_in[0];
    const float* K = (const float*)d_in[1];
    const float* V = (const float*)d_in[2];
    float* O = (float*)d_out;

    // Phase 1: all QK^T tiles (all rates) in one launch. 340 tiles/bg.
    qk_kernel<<<dim3(340, NBG), 256>>>(Q, K);

    // Phase 2: softmax on all 30720 score rows.
    softmax_kernel<<<30720, 256>>>();

    // Phase 3: P*V. r=1 covers every output row -> '='; rest accumulate
    // (r=2/4/8 write overlapping rows: must stay stream-ordered).
    static const int  Ls[4] = {2048, 1024, 512, 256};
    static const int  rs[4] = {1, 2, 4, 8};
    static const unsigned long long offs[4] = {OFF1, OFF2, OFF4, OFF8};
    for (int t = 0; t < 4; t++)
        pv_kernel<<<dim3(DIM / 128, Ls[t] / 128, NBG), 256>>>(V, O, rs[t], Ls[t], offs[t], t != 0);
}

// round 8
// speedup vs baseline: 1.2916x; 1.2916x over previous
#include <cuda_runtime.h>
#include <cuda_bf16.h>

// DilatedAttention: B=2, S=8192, D=1024, SEG=2048, rates {1,2,4,8}
// Phase 1: merged QK^T GEMM (all rates) -> score scratch      (1 launch)
// Phase 2: row softmax in place on scratch                    (1 launch)
// Phase 3: merged P*V GEMM all rates; r=1 -> d_out '=',
//          r=2/4/8 -> dense per-rate scratch                  (1 launch)
// Phase 4: merge r=2/4/8 scratch into d_out                   (1 launch)
//
// R4 evidence: smem crossbar bound (L1=77%, fma=41%); no broadcast dedup on
// LDS.128 (512B/warp-instr always). This version: 4 LDS.128/slice + register
// dup2 -> ~2190 crossbar cyc vs 2048 fma cyc per CTA-chunk (balanced).
// Smem rows padded to 132 floats (16B-aligned) to halve staging STS conflicts.

#define DIM 1024
#define SEG 2048
#define NBG 8   /* B * n_seg */
#define SW  132 /* padded smem row width (floats), 132*4 % 16 == 0 */

#define OFF1 0ull
#define OFF2 4194304ull            /* 2048^2 */
#define OFF4 5242880ull            /* +1024^2 */
#define OFF8 5505024ull            /* +512^2 */
#define PER_BG 5570560ull          /* +256^2 */

#define O2_R2 0ull
#define O2_R4 1048576ull           /* 1024*1024 */
#define O2_R8 1572864ull           /* +512*1024 */
#define PER_O2 1835008ull          /* +256*1024 */

__device__ __align__(16) float g_S[8ull * PER_BG];    // ~178 MB scores
__device__ __align__(16) float g_O2[8ull * PER_O2];   // ~59 MB partial outputs

typedef unsigned long long ull;

__device__ __forceinline__ ull dup2(float x) {
    ull r; asm("mov.b64 %0, {%1, %1};" : "=l"(r) : "f"(x)); return r;
}
__device__ __forceinline__ ull fma2(ull a, ull b, ull c) {
    ull d; asm("fma.rn.f32x2 %0, %1, %2, %3;" : "=l"(d) : "l"(a), "l"(b), "l"(c)); return d;
}
__device__ __forceinline__ float2 unpk(ull v) {
    float lo, hi; asm("mov.b64 {%0, %1}, %2;" : "=f"(lo), "=f"(hi) : "l"(v));
    float2 f; f.x = lo; f.y = hi; return f;
}

// ---------------------------------------------------------------------------
// Merged QK^T: for each rate r, S_r[LxL] = Qr[Lx1024] * Kr[Lx1024]^T.
// 128x128x16 tile, 256 threads, 8x8 microtile. grid=(340, 8).
// ---------------------------------------------------------------------------
__global__ __launch_bounds__(256, 2) void qk_kernel(
    const float* __restrict__ Q, const float* __restrict__ Kp)
{
    __shared__ __align__(16) float As[2][16][SW];
    __shared__ __align__(16) float Bs[2][16][SW];

    int t = blockIdx.x;
    int r, L; ull soff; int mtile, ntile;
    if (t < 256)      {          r = 1; L = 2048; soff = OFF1; mtile = t >> 4; ntile = t & 15; }
    else if (t < 320) { t -= 256; r = 2; L = 1024; soff = OFF2; mtile = t >> 3; ntile = t & 7; }
    else if (t < 336) { t -= 320; r = 4; L = 512;  soff = OFF4; mtile = t >> 2; ntile = t & 3; }
    else              { t -= 336; r = 8; L = 256;  soff = OFF8; mtile = t >> 1; ntile = t & 1; }

    const int tid   = threadIdx.x;
    const int bg    = blockIdx.y;
    const int mbase = mtile * 128;
    const int nbase = ntile * 128;

    const float* Qb = Q  + (size_t)bg * SEG * DIM;
    const float* Kb = Kp + (size_t)bg * SEG * DIM;
    float*       Sp = g_S + (size_t)bg * PER_BG + soff;

    const int lrow = tid >> 2;         // 0..63
    const int kq   = (tid & 3) << 2;   // 0,4,8,12
    const float* ag0  = Qb + (size_t)(mbase + lrow)      * r * DIM + kq;
    const float* ag1  = Qb + (size_t)(mbase + lrow + 64) * r * DIM + kq;
    const float* bgp0 = Kb + (size_t)(nbase + lrow)      * r * DIM + kq;
    const float* bgp1 = Kb + (size_t)(nbase + lrow + 64) * r * DIM + kq;

    const int tx = tid & 15, ty = tid >> 4;

    ull acc[8][4];
    #pragma unroll
    for (int i = 0; i < 8; i++)
        #pragma unroll
        for (int j = 0; j < 4; j++) acc[i][j] = 0ull;

    const int NC = DIM / 16;  // 64
    float4 ra0, ra1, rb0, rb1;

    ra0 = *(const float4*)(ag0);
    ra1 = *(const float4*)(ag1);
    rb0 = *(const float4*)(bgp0);
    rb1 = *(const float4*)(bgp1);
    #pragma unroll
    for (int j = 0; j < 4; j++) {
        As[0][kq + j][lrow]      = ((const float*)&ra0)[j];
        As[0][kq + j][lrow + 64] = ((const float*)&ra1)[j];
        Bs[0][kq + j][lrow]      = ((const float*)&rb0)[j];
        Bs[0][kq + j][lrow + 64] = ((const float*)&rb1)[j];
    }
    __syncthreads();

    for (int c = 0; c < NC; c++) {
        const int cur = c & 1;
        const bool more = (c + 1 < NC);
        if (more) {
            const int kc = (c + 1) * 16;
            ra0 = *(const float4*)(ag0 + kc);
            ra1 = *(const float4*)(ag1 + kc);
            rb0 = *(const float4*)(bgp0 + kc);
            rb1 = *(const float4*)(bgp1 + kc);
        }
        #pragma unroll
        for (int kk = 0; kk < 16; kk++) {
            float av[8];
            *(float4*)&av[0] = *(const float4*)&As[cur][kk][ty * 8];
            *(float4*)&av[4] = *(const float4*)&As[cur][kk][ty * 8 + 4];
            ulonglong2 b01 = *(const ulonglong2*)&Bs[cur][kk][tx * 8];
            ulonglong2 b23 = *(const ulonglong2*)&Bs[cur][kk][tx * 8 + 4];
            ull bb[4] = { b01.x, b01.y, b23.x, b23.y };
            #pragma unroll
            for (int i = 0; i < 8; i++) {
                ull ai = dup2(av[i]);
                #pragma unroll
                for (int jp = 0; jp < 4; jp++)
                    acc[i][jp] = fma2(ai, bb[jp], acc[i][jp]);
            }
        }
        if (more) {
            const int nxt = cur ^ 1;  // disjoint buffers: one barrier per chunk
            #pragma unroll
            for (int j = 0; j < 4; j++) {
                As[nxt][kq + j][lrow]      = ((const float*)&ra0)[j];
                As[nxt][kq + j][lrow + 64] = ((const float*)&ra1)[j];
                Bs[nxt][kq + j][lrow]      = ((const float*)&rb0)[j];
                Bs[nxt][kq + j][lrow + 64] = ((const float*)&rb1)[j];
            }
            __syncthreads();
        }
    }

    #pragma unroll
    for (int i = 0; i < 8; i++) {
        const int row = mbase + ty * 8 + i;
        float* p = Sp + (size_t)row * L + nbase + tx * 8;
        float2 c0 = unpk(acc[i][0]), c1 = unpk(acc[i][1]);
        float2 c2 = unpk(acc[i][2]), c3 = unpk(acc[i][3]);
        __stcs((float4*)p,       make_float4(c0.x, c0.y, c1.x, c1.y));
        __stcs((float4*)(p + 4), make_float4(c2.x, c2.y, c3.x, c3.y));
    }
}

// ---------------------------------------------------------------------------
// Softmax: one block per score row (30720 rows), smem-resident, in place.
// ---------------------------------------------------------------------------
__global__ __launch_bounds__(256) void softmax_kernel()
{
    __shared__ float buf[2048];
    __shared__ float red[8];

    const int idx = blockIdx.x;
    const int tid = threadIdx.x;
    const int lane = tid & 31, wid = tid >> 5;

    int L; ull base;
    if (idx < 16384)      { int bg = idx >> 11, row = idx & 2047; L = 2048; base = (ull)bg * PER_BG + OFF1 + (ull)row * 2048; }
    else if (idx < 24576) { int j = idx - 16384; int bg = j >> 10, row = j & 1023; L = 1024; base = (ull)bg * PER_BG + OFF2 + (ull)row * 1024; }
    else if (idx < 28672) { int j = idx - 24576; int bg = j >> 9,  row = j & 511;  L = 512;  base = (ull)bg * PER_BG + OFF4 + (ull)row * 512; }
    else                  { int j = idx - 28672; int bg = j >> 8,  row = j & 255;  L = 256;  base = (ull)bg * PER_BG + OFF8 + (ull)row * 256; }

    float* rp = g_S + base;

    float mx = -3.402823466e38f;
    for (int i = tid; i < L; i += 256) {
        float v = __ldcs(rp + i);
        buf[i] = v;
        mx = fmaxf(mx, v);
    }
    #pragma unroll
    for (int s = 16; s > 0; s >>= 1) mx = fmaxf(mx, __shfl_xor_sync(0xffffffffu, mx, s));
    if (lane == 0) red[wid] = mx;
    __syncthreads();
    if (wid == 0) {
        float m = red[lane & 7];
        #pragma unroll
        for (int s = 4; s > 0; s >>= 1) m = fmaxf(m, __shfl_xor_sync(0xffffffffu, m, s));
        if (lane == 0) red[0] = m;
    }
    __syncthreads();
    mx = red[0];

    float sum = 0.f;
    for (int i = tid; i < L; i += 256) {
        float e = __expf(buf[i] - mx);
        buf[i] = e;
        sum += e;
    }
    #pragma unroll
    for (int s = 16; s > 0; s >>= 1) sum += __shfl_xor_sync(0xffffffffu, sum, s);
    __syncthreads();
    if (lane == 0) red[wid] = sum;
    __syncthreads();
    if (wid == 0) {
        float m = red[lane & 7];
        #pragma unroll
        for (int s = 4; s > 0; s >>= 1) m += __shfl_xor_sync(0xffffffffu, m, s);
        if (lane == 0) red[0] = m;
    }
    __syncthreads();
    const float inv = 1.0f / red[0];
    for (int i = tid; i < L; i += 256) __stcs(rp + i, buf[i] * inv);
}

// ---------------------------------------------------------------------------
// Merged P*V: all rates in one launch. grid=(240, 8).
// r=1 writes '=' into O (covers every row); r=2/4/8 write dense scratch.
// ---------------------------------------------------------------------------
__global__ __launch_bounds__(256, 2) void pv_kernel(
    const float* __restrict__ V, float* __restrict__ O)
{
    __shared__ __align__(16) float As[2][16][SW];
    __shared__ __align__(16) float Bs[2][16][SW];

    int t = blockIdx.x;
    int r, L; ull soff, ooff; int direct; int mtile, ntile;
    if (t < 128)      {          r = 1; L = 2048; soff = OFF1; ooff = 0;     direct = 1; mtile = t >> 3; ntile = t & 7; }
    else if (t < 192) { t -= 128; r = 2; L = 1024; soff = OFF2; ooff = O2_R2; direct = 0; mtile = t >> 3; ntile = t & 7; }
    else if (t < 224) { t -= 192; r = 4; L = 512;  soff = OFF4; ooff = O2_R4; direct = 0; mtile = t >> 3; ntile = t & 7; }
    else              { t -= 224; r = 8; L = 256;  soff = OFF8; ooff = O2_R8; direct = 0; mtile = t >> 3; ntile = t & 7; }

    const int tid   = threadIdx.x;
    const int bg    = blockIdx.y;
    const int mbase = mtile * 128;
    const int nbase = ntile * 128;

    const float* Vb = V + (size_t)bg * SEG * DIM;
    const float* P  = g_S + (size_t)bg * PER_BG + soff;

    const int lrow = tid >> 2;
    const int kq   = (tid & 3) << 2;
    const float* pg0 = P + (size_t)(mbase + lrow)      * L + kq;
    const float* pg1 = P + (size_t)(mbase + lrow + 64) * L + kq;

    const int krow = tid >> 5;          // 0..7
    const int vcol = (tid & 31) << 2;   // 0..124

    const int tx = tid & 15, ty = tid >> 4;

    ull acc[8][4];
    #pragma unroll
    for (int i = 0; i < 8; i++)
        #pragma unroll
        for (int j = 0; j < 4; j++) acc[i][j] = 0ull;

    const int NC = L / 16;
    float4 ra0, ra1, rb0, rb1;

    ra0 = __ldcs((const float4*)(pg0));
    ra1 = __ldcs((const float4*)(pg1));
    rb0 = *(const float4*)(Vb + (size_t)krow       * r * DIM + nbase + vcol);
    rb1 = *(const float4*)(Vb + (size_t)(krow + 8) * r * DIM + nbase + vcol);
    #pragma unroll
    for (int j = 0; j < 4; j++) {
        As[0][kq + j][lrow]      = ((const float*)&ra0)[j];
        As[0][kq + j][lrow + 64] = ((const float*)&ra1)[j];
    }
    *(float4*)&Bs[0][krow][vcol]     = rb0;
    *(float4*)&Bs[0][krow + 8][vcol] = rb1;
    __syncthreads();

    for (int c = 0; c < NC; c++) {
        const int cur = c & 1;
        const bool more = (c + 1 < NC);
        if (more) {
            const int kc = (c + 1) * 16;
            ra0 = __ldcs((const float4*)(pg0 + kc));
            ra1 = __ldcs((const float4*)(pg1 + kc));
            rb0 = *(const float4*)(Vb + (size_t)(kc + krow)     * r * DIM + nbase + vcol);
            rb1 = *(const float4*)(Vb + (size_t)(kc + krow + 8) * r * DIM + nbase + vcol);
        }
        #pragma unroll
        for (int kk = 0; kk < 16; kk++) {
            float av[8];
            *(float4*)&av[0] = *(const float4*)&As[cur][kk][ty * 8];
            *(float4*)&av[4] = *(const float4*)&As[cur][kk][ty * 8 + 4];
            ulonglong2 b01 = *(const ulonglong2*)&Bs[cur][kk][tx * 8];
            ulonglong2 b23 = *(const ulonglong2*)&Bs[cur][kk][tx * 8 + 4];
            ull bb[4] = { b01.x, b01.y, b23.x, b23.y };
            #pragma unroll
            for (int i = 0; i < 8; i++) {
                ull ai = dup2(av[i]);
                #pragma unroll
                for (int jp = 0; jp < 4; jp++)
                    acc[i][jp] = fma2(ai, bb[jp], acc[i][jp]);
            }
        }
        if (more) {
            const int nxt = cur ^ 1;
            #pragma unroll
            for (int j = 0; j < 4; j++) {
                As[nxt][kq + j][lrow]      = ((const float*)&ra0)[j];
                As[nxt][kq + j][lrow + 64] = ((const float*)&ra1)[j];
            }
            *(float4*)&Bs[nxt][krow][vcol]     = rb0;
            *(float4*)&Bs[nxt][krow + 8][vcol] = rb1;
            __syncthreads();
        }
    }

    float* Od = direct ? (O + (size_t)bg * SEG * DIM)
                       : (g_O2 + (size_t)bg * PER_O2 + ooff);

    #pragma unroll
    for (int i = 0; i < 8; i++) {
        const int qrow = mbase + ty * 8 + i;
        float* p = Od + (size_t)qrow * DIM + nbase + tx * 8;   // r=1 stride == DIM
        float2 c0 = unpk(acc[i][0]), c1 = unpk(acc[i][1]);
        float2 c2 = unpk(acc[i][2]), c3 = unpk(acc[i][3]);
        *(float4*)p       = make_float4(c0.x, c0.y, c1.x, c1.y);
        *(float4*)(p + 4) = make_float4(c2.x, c2.y, c3.x, c3.y);
    }
}

// ---------------------------------------------------------------------------
// Merge r=2/4/8 partial outputs into O. One block per r=2-domain row.
// grid = 8 bg * 1024 rows; 256 threads; one float4 per thread.
// ---------------------------------------------------------------------------
__global__ __launch_bounds__(256) void merge_kernel(float* __restrict__ O)
{
    const int b   = blockIdx.x;
    const int bg  = b >> 10;
    const int i   = b & 1023;          // row in r=2 domain
    const int tid = threadIdx.x;

    const float4* R2 = (const float4*)(g_O2 + (size_t)bg * PER_O2 + O2_R2);
    const float4* R4 = (const float4*)(g_O2 + (size_t)bg * PER_O2 + O2_R4);
    const float4* R8 = (const float4*)(g_O2 + (size_t)bg * PER_O2 + O2_R8);
    float4* Ob = (float4*)(O + (size_t)bg * SEG * DIM);

    const size_t oidx = (size_t)(2 * i) * 256 + tid;   // row 2i, float4 col tid
    float4 v = Ob[oidx];
    float4 a = R2[(size_t)i * 256 + tid];
    v.x += a.x; v.y += a.y; v.z += a.z; v.w += a.w;
    if ((i & 1) == 0) {
        float4 c = R4[(size_t)(i >> 1) * 256 + tid];
        v.x += c.x; v.y += c.y; v.z += c.z; v.w += c.w;
    }
    if ((i & 3) == 0) {
        float4 c = R8[(size_t)(i >> 2) * 256 + tid];
        v.x += c.x; v.y += c.y; v.z += c.z; v.w += c.w;
    }
    Ob[oidx] = v;
}

extern "C" void kernel_launch(void* const* d_in, const int* in_sizes, int n_in,
                              void* d_out, int out_size)
{
    const float* Q = (const float*)d_in[0];
    const float* K = (const float*)d_in[1];
    const float* V = (const float*)d_in[2];
    float* O = (float*)d_out;

    qk_kernel<<<dim3(340, NBG), 256>>>(Q, K);          // all QK^T tiles
    softmax_kernel<<<30720, 256>>>();                  // all score rows
    pv_kernel<<<dim3(240, NBG), 256>>>(V, O);          // all P*V tiles
    merge_kernel<<<8192, 256>>>(O);                    // fold r=2/4/8 into O
}